// round 4
// baseline (speedup 1.0000x reference)
#include <cuda_runtime.h>
#include <math.h>

#define NN 50000
#define EE 800000
#define FF 64

// ---------------- scratch (device globals; no allocation allowed) ----------------
__device__ float g_h[NN * FF];                // current node features
__device__ float g_AB[NN * 2 * FF];           // per-node A (cols 0..63) and B (cols 64..127)
__device__ float g_cat[(size_t)NN * 5 * FF];  // [N,320] fused features
__device__ int   g_deg[NN];
__device__ int   g_ptr[NN + 1];
__device__ int   g_cur[NN];
__device__ int   g_csrc[EE];
__device__ float g_Wab[2][FF * 2 * FF];       // [64][128] rearranged pre_W per layer
__device__ float g_PW[2][5 * FF * FF];        // [320][64] folded post_W @ lin_W
__device__ float g_Pb[2][FF];                 // folded bias

// device-side buffer id -> pointer (so kernel_launch never queries symbols)
__device__ __forceinline__ const float* resolve_src(int id, const float* ext) {
    switch (id) {
        case 0: return g_h;
        case 1: return g_AB;
        case 2: return g_cat;
        case 3: return g_Wab[0];
        case 4: return g_Wab[1];
        case 5: return g_PW[0];
        case 6: return g_PW[1];
        case 7: return g_Pb[0];
        case 8: return g_Pb[1];
        default: return ext;
    }
}
__device__ __forceinline__ float* resolve_dst(int id) {
    switch (id) {
        case 0: return g_h;
        case 1: return g_AB;
        default: return g_cat;
    }
}

// ---------------- CSR build ----------------
__global__ void k_zero() {
    int i = blockIdx.x * blockDim.x + threadIdx.x;
    if (i < NN) g_deg[i] = 0;
}

__global__ void k_deg(const int* __restrict__ dst) {
    int e = blockIdx.x * blockDim.x + threadIdx.x;
    if (e < EE) atomicAdd(&g_deg[dst[e]], 1);
}

__global__ void k_scan() {  // single block, 1024 threads
    __shared__ int sdata[1024];
    __shared__ int carry;
    int tid = threadIdx.x;
    if (tid == 0) { carry = 0; g_ptr[0] = 0; }
    __syncthreads();
    for (int base = 0; base < NN; base += 1024) {
        int i = base + tid;
        int v = (i < NN) ? g_deg[i] : 0;
        sdata[tid] = v;
        __syncthreads();
        for (int off = 1; off < 1024; off <<= 1) {
            int t = (tid >= off) ? sdata[tid - off] : 0;
            __syncthreads();
            sdata[tid] += t;
            __syncthreads();
        }
        if (i < NN) {
            int incl = carry + sdata[tid];
            g_ptr[i + 1] = incl;
            g_cur[i] = incl - v;   // exclusive (fill cursor)
        }
        __syncthreads();
        if (tid == 1023) carry += sdata[1023];
        __syncthreads();
    }
}

__global__ void k_fill(const int* __restrict__ src, const int* __restrict__ dst) {
    int e = blockIdx.x * blockDim.x + threadIdx.x;
    if (e < EE) {
        int slot = atomicAdd(&g_cur[dst[e]], 1);
        g_csrc[slot] = src[e];
    }
}

// ---------------- weight prep ----------------
// Wab[k][c]: c<64 -> preW[k][c] (dst half), c>=64 -> preW[64+k][c-64] (src half)
__global__ void k_wab(const float* __restrict__ preW, int layer) {
    int idx = blockIdx.x * blockDim.x + threadIdx.x;
    if (idx < 64 * 128) {
        int k = idx / 128, c = idx % 128;
        g_Wab[layer][idx] = (c < 64) ? preW[k * 64 + c] : preW[(64 + k) * 64 + (c - 64)];
    }
}

// PW = post_W @ lin_W  [320,64];  Pb = post_b @ lin_W + lin_b
__global__ void k_fold(const float* __restrict__ postW, const float* __restrict__ postb,
                       const float* __restrict__ linW, const float* __restrict__ linb,
                       int layer) {
    int row = blockIdx.x;
    int c = threadIdx.x;
    if (row < 320) {
        float s = 0.f;
        for (int k = 0; k < 64; k++) s += postW[row * 64 + k] * linW[k * 64 + c];
        g_PW[layer][row * 64 + c] = s;
    } else {
        float s = linb[c];
        for (int k = 0; k < 64; k++) s += postb[k] * linW[k * 64 + c];
        g_Pb[layer][c] = s;
    }
}

// ---------------- generic tiled SGEMM: OUT = act(A[N,K] @ W[K,NCOL] + bias) ----------------
// ACT: 0 none, 1 leaky(0.2), 2 relu.  AID/WID/BID: -1 => use ext pointer; BID=-2 => no bias.
template <int K, int NCOL, int ACT, int AID, int WID, int BID, int OID>
__global__ void __launch_bounds__(256) k_gemm(const float* __restrict__ Aext,
                                              const float* __restrict__ Wext,
                                              const float* __restrict__ Bext,
                                              int nrows) {
    const float* A = resolve_src(AID, Aext);
    const float* W = resolve_src(WID, Wext);
    const float* bias = (BID == -2) ? (const float*)0 : resolve_src(BID, Bext);
    float* C = resolve_dst(OID);

    constexpr int KC = 32;
    constexpr int CG = NCOL / 4;   // col thread groups
    constexpr int RT = 256 / CG;   // row threads
    constexpr int TM = RT * 4;     // tile rows
    __shared__ float As[KC][TM];
    __shared__ float Ws[KC][NCOL];
    int tid = threadIdx.x;
    int tx = tid % CG, ty = tid / CG;
    int row0 = blockIdx.x * TM;
    float acc[4][4] = {};
    for (int kc = 0; kc < K; kc += KC) {
        // load A tile (TM x KC), transposed into As[k][row]
        #pragma unroll
        for (int f = 0; f < (TM * KC / 4) / 256; f++) {
            int idx = tid + f * 256;
            int r = idx / (KC / 4);
            int kq = idx % (KC / 4);
            float4 v = make_float4(0.f, 0.f, 0.f, 0.f);
            if (row0 + r < nrows)
                v = *reinterpret_cast<const float4*>(&A[(size_t)(row0 + r) * K + kc + kq * 4]);
            As[kq * 4 + 0][r] = v.x;
            As[kq * 4 + 1][r] = v.y;
            As[kq * 4 + 2][r] = v.z;
            As[kq * 4 + 3][r] = v.w;
        }
        // load W tile (KC x NCOL)
        #pragma unroll
        for (int f = 0; f < (KC * NCOL / 4) / 256; f++) {
            int idx = tid + f * 256;
            int kr = idx / CG;
            int cq = idx % CG;
            *reinterpret_cast<float4*>(&Ws[kr][cq * 4]) =
                *reinterpret_cast<const float4*>(&W[(size_t)(kc + kr) * NCOL + cq * 4]);
        }
        __syncthreads();
        #pragma unroll
        for (int k = 0; k < KC; k++) {
            float4 a = *reinterpret_cast<const float4*>(&As[k][ty * 4]);
            float4 w = *reinterpret_cast<const float4*>(&Ws[k][tx * 4]);
            float av[4] = {a.x, a.y, a.z, a.w};
            float wv[4] = {w.x, w.y, w.z, w.w};
            #pragma unroll
            for (int r = 0; r < 4; r++)
                #pragma unroll
                for (int c = 0; c < 4; c++) acc[r][c] = fmaf(av[r], wv[c], acc[r][c]);
        }
        __syncthreads();
    }
    #pragma unroll
    for (int r = 0; r < 4; r++) {
        int row = row0 + ty * 4 + r;
        if (row < nrows) {
            #pragma unroll
            for (int c = 0; c < 4; c++) {
                float v = acc[r][c];
                int col = tx * 4 + c;
                if (bias) v += bias[col];
                if (ACT == 1) v = (v > 0.f) ? v : 0.2f * v;
                if (ACT == 2) v = fmaxf(v, 0.f);
                C[(size_t)row * NCOL + col] = v;
            }
        }
    }
}

// ---------------- aggregation: segment sum/max of B over sorted CSR, build cat ----------------
// Expected max degree ~45 (Binomial(800k, 1/50k) over 50k nodes); MAXD=192 is ample.
#define MAXD 192
__global__ void __launch_bounds__(256) k_agg(const float* __restrict__ preb) {
    __shared__ int ssrc[4][MAXD];
    int g = threadIdx.x >> 6;
    int t = threadIdx.x & 63;
    int node = blockIdx.x * 4 + g;
    bool valid = node < NN;
    int beg = 0, end = 0;
    if (valid) { beg = g_ptr[node]; end = g_ptr[node + 1]; }
    int deg = end - beg;
    // parallel load of src list into shared
    if (valid && deg <= MAXD) {
        for (int e = t; e < deg; e += 64) ssrc[g][e] = g_csrc[beg + e];
    }
    __syncthreads();
    // canonical order: insertion sort by one lane (deterministic FP sum order)
    if (valid && t == 0 && deg <= MAXD) {
        for (int i = 1; i < deg; i++) {
            int v = ssrc[g][i];
            int j = i - 1;
            while (j >= 0 && ssrc[g][j] > v) { ssrc[g][j + 1] = ssrc[g][j]; j--; }
            ssrc[g][j + 1] = v;
        }
    }
    __syncthreads();
    if (!valid) return;
    float sum = 0.f, mx = -3.4e38f;
    if (deg <= MAXD) {
        for (int e = 0; e < deg; e++) {
            float v = g_AB[(size_t)ssrc[g][e] * 128 + 64 + t];
            sum += v;
            mx = fmaxf(mx, v);
        }
    } else {
        for (int e = beg; e < end; e++) {
            float v = g_AB[(size_t)g_csrc[e] * 128 + 64 + t];
            sum += v;
            mx = fmaxf(mx, v);
        }
    }
    float hx = g_h[node * 64 + t];
    float* cr = &g_cat[(size_t)node * 320];
    cr[t] = hx;
    if (deg == 0) {
        cr[64 + t] = 0.f; cr[128 + t] = 0.f; cr[192 + t] = 0.f; cr[256 + t] = 0.f;
    } else {
        float bA = g_AB[(size_t)node * 128 + t] + preb[t];
        float mean = bA + sum / (float)deg;
        float mxv = bA + mx;
        float sa = 2.8332133440562162f / logf((float)deg + 1.0f);  // log(17)/log(deg+1)
        float sl = (float)deg * 0.0625f;                            // deg/16
        cr[64 + t] = mean * sa;
        cr[128 + t] = mxv * sa;
        cr[192 + t] = mean * sl;
        cr[256 + t] = mxv * sl;
    }
}

// ---------------- final projection: out[i] = h[i] . W2 + b2 ----------------
__global__ void k_out(const float* __restrict__ W2, const float* __restrict__ b2,
                      float* __restrict__ out) {
    int node = blockIdx.x * 8 + (threadIdx.x >> 5);
    int lane = threadIdx.x & 31;
    if (node >= NN) return;
    float v = g_h[node * 64 + lane] * W2[lane] + g_h[node * 64 + 32 + lane] * W2[32 + lane];
    #pragma unroll
    for (int o = 16; o; o >>= 1) v += __shfl_xor_sync(0xffffffffu, v, o);
    if (lane == 0) out[node] = v + b2[0];
}

// ---------------- launch: kernel launches ONLY, no runtime API calls ----------------
extern "C" void kernel_launch(void* const* d_in, const int* in_sizes, int n_in,
                              void* d_out, int out_size) {
    (void)in_sizes; (void)n_in; (void)out_size;
    const float* x   = (const float*)d_in[0];
    const int*   ei  = (const int*)d_in[2];
    const float* W0  = (const float*)d_in[3];
    const float* b0  = (const float*)d_in[4];
    const float* preW1  = (const float*)d_in[5];
    const float* preB1  = (const float*)d_in[6];
    const float* postW1 = (const float*)d_in[7];
    const float* postB1 = (const float*)d_in[8];
    const float* linW1  = (const float*)d_in[9];
    const float* linB1  = (const float*)d_in[10];
    const float* preW2  = (const float*)d_in[11];
    const float* preB2  = (const float*)d_in[12];
    const float* postW2 = (const float*)d_in[13];
    const float* postB2 = (const float*)d_in[14];
    const float* linW2  = (const float*)d_in[15];
    const float* linB2  = (const float*)d_in[16];
    const float* W2 = (const float*)d_in[17];
    const float* b2 = (const float*)d_in[18];
    float* out = (float*)d_out;

    const int* src = ei;
    const int* dst = ei + EE;

    // CSR build (no memset — zero via kernel)
    k_zero<<<(NN + 255) / 256, 256>>>();
    k_deg<<<(EE + 255) / 256, 256>>>(dst);
    k_scan<<<1, 1024>>>();
    k_fill<<<(EE + 255) / 256, 256>>>(src, dst);

    // weight prep (both layers)
    k_wab<<<(64 * 128 + 255) / 256, 256>>>(preW1, 0);
    k_wab<<<(64 * 128 + 255) / 256, 256>>>(preW2, 1);
    k_fold<<<321, 64>>>(postW1, postB1, linW1, linB1, 0);
    k_fold<<<321, 64>>>(postW2, postB2, linW2, linB2, 1);

    // h0 = leaky_relu(x @ W0 + b0)   (ext A, ext W, ext bias -> g_h)
    k_gemm<128, 64, 1, -1, -1, -1, 0><<<(NN + 63) / 64, 256>>>(x, W0, b0, NN);

    // layer 1
    k_gemm<64, 128, 0, 0, 3, -2, 1><<<(NN + 31) / 32, 256>>>(0, 0, 0, NN); // g_h @ Wab0 -> g_AB
    k_agg<<<(NN + 3) / 4, 256>>>(preB1);
    k_gemm<320, 64, 2, 2, 5, 7, 0><<<(NN + 63) / 64, 256>>>(0, 0, 0, NN);  // g_cat @ PW0 + Pb0 -> g_h

    // layer 2
    k_gemm<64, 128, 0, 0, 4, -2, 1><<<(NN + 31) / 32, 256>>>(0, 0, 0, NN); // g_h @ Wab1 -> g_AB
    k_agg<<<(NN + 3) / 4, 256>>>(preB2);
    k_gemm<320, 64, 2, 2, 6, 8, 0><<<(NN + 63) / 64, 256>>>(0, 0, 0, NN);  // g_cat @ PW1 + Pb1 -> g_h

    // final scalar head
    k_out<<<(NN + 7) / 8, 256>>>(W2, b2, out);
}

// round 6
// speedup vs baseline: 1.4606x; 1.4606x over previous
#include <cuda_runtime.h>
#include <math.h>

#define NN 50000
#define EE 800000
#define FF 64

// ---------------- scratch (device globals; no allocation allowed) ----------------
__device__ float g_h[NN * FF];                // current node features
__device__ float g_AB[NN * 2 * FF];           // per-node A (cols 0..63) and B (cols 64..127)
__device__ float g_cat[(size_t)NN * 5 * FF];  // [N,320] fused features
__device__ int   g_deg[NN];
__device__ int   g_ptr[NN + 1];
__device__ int   g_cur[NN];
__device__ int   g_csrc[EE];
__device__ float g_Wab[2][FF * 2 * FF];       // [64][128] rearranged pre_W per layer
__device__ float g_PW[2][5 * FF * FF];        // [320][64] folded post_W @ lin_W
__device__ float g_Pb[2][FF];                 // folded bias

// device-side buffer id -> pointer (kernel_launch makes no runtime API calls)
__device__ __forceinline__ const float* resolve_src(int id, const float* ext) {
    switch (id) {
        case 0: return g_h;
        case 1: return g_AB;
        case 2: return g_cat;
        case 3: return g_Wab[0];
        case 4: return g_Wab[1];
        case 5: return g_PW[0];
        case 6: return g_PW[1];
        case 7: return g_Pb[0];
        case 8: return g_Pb[1];
        default: return ext;
    }
}
__device__ __forceinline__ float* resolve_dst(int id) {
    switch (id) {
        case 0: return g_h;
        case 1: return g_AB;
        default: return g_cat;
    }
}

// ---------------- fused prep: zero g_deg + rearrange pre_W (both) + fold post@lin (both) ----
// block ranges: [0,196) zero | [196,228) wab0 | [228,260) wab1 | [260,341) fold0 | [341,422) fold1
__global__ void k_prep(const float* __restrict__ preW1, const float* __restrict__ preW2,
                       const float* __restrict__ postW1, const float* __restrict__ postb1,
                       const float* __restrict__ linW1, const float* __restrict__ linb1,
                       const float* __restrict__ postW2, const float* __restrict__ postb2,
                       const float* __restrict__ linW2, const float* __restrict__ linb2) {
    int b = blockIdx.x, tid = threadIdx.x;
    if (b < 196) {
        int i = b * 256 + tid;
        if (i < NN) g_deg[i] = 0;
        return;
    }
    if (b < 260) {  // wab
        int layer = (b < 228) ? 0 : 1;
        const float* preW = layer ? preW2 : preW1;
        int idx = (b - (layer ? 228 : 196)) * 256 + tid;  // < 8192
        int k = idx >> 7, c = idx & 127;
        g_Wab[layer][idx] = (c < 64) ? preW[k * 64 + c] : preW[(64 + k) * 64 + (c - 64)];
        return;
    }
    {   // fold
        int layer = (b < 341) ? 0 : 1;
        const float* postW = layer ? postW2 : postW1;
        const float* postb = layer ? postb2 : postb1;
        const float* linW  = layer ? linW2  : linW1;
        const float* linb  = layer ? linb2  : linb1;
        int idx = (b - (layer ? 341 : 260)) * 256 + tid;
        if (idx >= 321 * 64) return;
        int row = idx >> 6, c = idx & 63;
        if (row < 320) {
            float s = 0.f;
            #pragma unroll 8
            for (int k = 0; k < 64; k++) s += postW[row * 64 + k] * linW[k * 64 + c];
            g_PW[layer][row * 64 + c] = s;
        } else {
            float s = linb[c];
            #pragma unroll 8
            for (int k = 0; k < 64; k++) s += postb[k] * linW[k * 64 + c];
            g_Pb[layer][c] = s;
        }
    }
}

// ---------------- CSR build ----------------
__global__ void k_deg(const int* __restrict__ dst) {
    int e = blockIdx.x * blockDim.x + threadIdx.x;
    if (e < EE) atomicAdd(&g_deg[dst[e]], 1);
}

// single block, 1024 threads, shfl-based scan (4 barriers per 1024-tile)
__global__ void k_scan() {
    __shared__ int wsum[32];
    __shared__ int carry_s;
    int tid = threadIdx.x, lane = tid & 31, wid = tid >> 5;
    if (tid == 0) { carry_s = 0; g_ptr[0] = 0; }
    __syncthreads();
    for (int base = 0; base < NN; base += 1024) {
        int i = base + tid;
        int v = (i < NN) ? g_deg[i] : 0;
        int x = v;
        #pragma unroll
        for (int off = 1; off < 32; off <<= 1) {
            int y = __shfl_up_sync(0xffffffffu, x, off);
            if (lane >= off) x += y;
        }
        if (lane == 31) wsum[wid] = x;
        __syncthreads();
        if (wid == 0) {
            int s = wsum[lane];
            #pragma unroll
            for (int off = 1; off < 32; off <<= 1) {
                int y = __shfl_up_sync(0xffffffffu, s, off);
                if (lane >= off) s += y;
            }
            wsum[lane] = s;
        }
        __syncthreads();
        int incl = x + (wid ? wsum[wid - 1] : 0) + carry_s;
        if (i < NN) { g_ptr[i + 1] = incl; g_cur[i] = incl - v; }
        __syncthreads();
        if (tid == 1023) carry_s = incl;
        __syncthreads();
    }
}

__global__ void k_fill(const int* __restrict__ src, const int* __restrict__ dst) {
    int e = blockIdx.x * blockDim.x + threadIdx.x;
    if (e < EE) {
        int slot = atomicAdd(&g_cur[dst[e]], 1);
        g_csrc[slot] = src[e];
    }
}

// ---------------- tiled SGEMM: OUT = act(A[N,K] @ W[K,NCOL] + bias), 8x4 per thread ----------
// ACT: 0 none, 1 leaky(0.2), 2 relu.  AID/WID/BID: -1 => ext pointer; BID=-2 => no bias.
// FINAL: fuse out[row] = relu(row) . W2 + b2 (NCOL must be 64), writes outp instead of C.
template <int K, int NCOL, int ACT, int AID, int WID, int BID, int OID, int FINAL>
__global__ void __launch_bounds__(256) k_gemm(const float* __restrict__ Aext,
                                              const float* __restrict__ Wext,
                                              const float* __restrict__ Bext,
                                              const float* __restrict__ W2ext,
                                              const float* __restrict__ b2ext,
                                              float* __restrict__ outp,
                                              int nrows) {
    const float* A = resolve_src(AID, Aext);
    const float* W = resolve_src(WID, Wext);
    const float* bias = (BID == -2) ? (const float*)0 : resolve_src(BID, Bext);
    float* C = resolve_dst(OID);

    constexpr int KC = 32;
    constexpr int CG = NCOL / 4;   // col thread groups (16 or 32)
    constexpr int RT = 256 / CG;   // row threads (16 or 8)
    constexpr int TM = RT * 8;     // tile rows (128 or 64)
    __shared__ float As[KC][TM];
    __shared__ float Ws[KC][NCOL];
    int tid = threadIdx.x;
    int tx = tid % CG, ty = tid / CG;
    int row0 = blockIdx.x * TM;
    float acc[8][4] = {};
    for (int kc = 0; kc < K; kc += KC) {
        // load A tile (TM x KC), transposed into As[k][row]
        #pragma unroll
        for (int f = 0; f < (TM * KC / 4) / 256; f++) {
            int idx = tid + f * 256;
            int r = idx / (KC / 4);
            int kq = idx % (KC / 4);
            float4 v = make_float4(0.f, 0.f, 0.f, 0.f);
            if (row0 + r < nrows)
                v = *reinterpret_cast<const float4*>(&A[(size_t)(row0 + r) * K + kc + kq * 4]);
            As[kq * 4 + 0][r] = v.x;
            As[kq * 4 + 1][r] = v.y;
            As[kq * 4 + 2][r] = v.z;
            As[kq * 4 + 3][r] = v.w;
        }
        // load W tile (KC x NCOL)
        #pragma unroll
        for (int f = 0; f < (KC * NCOL / 4) / 256; f++) {
            int idx = tid + f * 256;
            int kr = idx / CG;
            int cq = idx % CG;
            *reinterpret_cast<float4*>(&Ws[kr][cq * 4]) =
                *reinterpret_cast<const float4*>(&W[(size_t)(kc + kr) * NCOL + cq * 4]);
        }
        __syncthreads();
        #pragma unroll
        for (int k = 0; k < KC; k++) {
            float4 a0 = *reinterpret_cast<const float4*>(&As[k][ty * 8]);
            float4 a1 = *reinterpret_cast<const float4*>(&As[k][ty * 8 + 4]);
            float4 w = *reinterpret_cast<const float4*>(&Ws[k][tx * 4]);
            float av[8] = {a0.x, a0.y, a0.z, a0.w, a1.x, a1.y, a1.z, a1.w};
            float wv[4] = {w.x, w.y, w.z, w.w};
            #pragma unroll
            for (int r = 0; r < 8; r++)
                #pragma unroll
                for (int c = 0; c < 4; c++) acc[r][c] = fmaf(av[r], wv[c], acc[r][c]);
        }
        __syncthreads();
    }
    if (FINAL) {
        // out[row] = sum_col relu(v[col]) * W2[col] + b2  (NCOL=64, CG=16)
        float w2r[4];
        #pragma unroll
        for (int c = 0; c < 4; c++) w2r[c] = W2ext[tx * 4 + c];
        float b2v = b2ext[0];
        #pragma unroll
        for (int r = 0; r < 8; r++) {
            int row = row0 + ty * 8 + r;
            float p = 0.f;
            #pragma unroll
            for (int c = 0; c < 4; c++) {
                float v = acc[r][c];
                if (bias) v += bias[tx * 4 + c];
                v = fmaxf(v, 0.f);
                p = fmaf(v, w2r[c], p);
            }
            // reduce across the 16 col-threads (contiguous lanes within a 16-lane half-warp)
            #pragma unroll
            for (int off = 8; off; off >>= 1) p += __shfl_xor_sync(0xffffffffu, p, off);
            if (tx == 0 && row < nrows) outp[row] = p + b2v;
        }
    } else {
        #pragma unroll
        for (int r = 0; r < 8; r++) {
            int row = row0 + ty * 8 + r;
            if (row < nrows) {
                #pragma unroll
                for (int c = 0; c < 4; c++) {
                    float v = acc[r][c];
                    int col = tx * 4 + c;
                    if (bias) v += bias[col];
                    if (ACT == 1) v = (v > 0.f) ? v : 0.2f * v;
                    if (ACT == 2) v = fmaxf(v, 0.f);
                    C[(size_t)row * NCOL + col] = v;
                }
            }
        }
    }
}

// ---------------- aggregation: segment sum/max of B over sorted CSR, build cat ----------------
// Max expected degree ~40 (Binomial(800k, 1/50k) over 50k nodes); MAXD=192 is ample headroom.
// Canonical order via rank-sort (no loops around barriers; trivially deadlock-free).
#define MAXD 192
__global__ void __launch_bounds__(256) k_agg(const float* __restrict__ preb) {
    __shared__ int ssrc[4][MAXD];
    __shared__ int ssrt[4][MAXD];
    int g = threadIdx.x >> 6;
    int t = threadIdx.x & 63;
    int node = blockIdx.x * 4 + g;
    bool valid = node < NN;
    int beg = 0, end = 0;
    if (valid) { beg = g_ptr[node]; end = g_ptr[node + 1]; }
    int deg = end - beg;
    bool small = valid && (deg <= MAXD);
    // parallel load of src list into shared
    if (small) {
        for (int e = t; e < deg; e += 64) ssrc[g][e] = g_csrc[beg + e];
    }
    __syncthreads();
    // rank-sort: rank(v_i) = #{v_j < v_i} + #{v_j == v_i && j < i}; scatter to ssrt
    if (small) {
        for (int i = t; i < deg; i += 64) {
            int v = ssrc[g][i];
            int rank = 0;
            for (int j = 0; j < deg; j++) {
                int u = ssrc[g][j];
                rank += (u < v) || (u == v && j < i);
            }
            ssrt[g][rank] = v;
        }
    }
    __syncthreads();
    if (!valid) return;
    float sum = 0.f, mx = -3.4e38f;
    if (small) {
        #pragma unroll 4
        for (int e = 0; e < deg; e++) {
            float v = g_AB[(size_t)ssrt[g][e] * 128 + 64 + t];
            sum += v;
            mx = fmaxf(mx, v);
        }
    } else {
        for (int e = beg; e < end; e++) {
            float v = g_AB[(size_t)g_csrc[e] * 128 + 64 + t];
            sum += v;
            mx = fmaxf(mx, v);
        }
    }
    float hx = g_h[node * 64 + t];
    float* cr = &g_cat[(size_t)node * 320];
    cr[t] = hx;
    if (deg == 0) {
        cr[64 + t] = 0.f; cr[128 + t] = 0.f; cr[192 + t] = 0.f; cr[256 + t] = 0.f;
    } else {
        float bA = g_AB[(size_t)node * 128 + t] + preb[t];
        float mean = bA + sum / (float)deg;
        float mxv = bA + mx;
        float sa = 2.8332133440562162f / logf((float)deg + 1.0f);  // log(17)/log(deg+1)
        float sl = (float)deg * 0.0625f;                            // deg/16
        cr[64 + t] = mean * sa;
        cr[128 + t] = mxv * sa;
        cr[192 + t] = mean * sl;
        cr[256 + t] = mxv * sl;
    }
}

// ---------------- launch: kernel launches ONLY ----------------
extern "C" void kernel_launch(void* const* d_in, const int* in_sizes, int n_in,
                              void* d_out, int out_size) {
    (void)in_sizes; (void)n_in; (void)out_size;
    const float* x   = (const float*)d_in[0];
    const int*   ei  = (const int*)d_in[2];
    const float* W0  = (const float*)d_in[3];
    const float* b0  = (const float*)d_in[4];
    const float* preW1  = (const float*)d_in[5];
    const float* preB1  = (const float*)d_in[6];
    const float* postW1 = (const float*)d_in[7];
    const float* postB1 = (const float*)d_in[8];
    const float* linW1  = (const float*)d_in[9];
    const float* linB1  = (const float*)d_in[10];
    const float* preW2  = (const float*)d_in[11];
    const float* preB2  = (const float*)d_in[12];
    const float* postW2 = (const float*)d_in[13];
    const float* postB2 = (const float*)d_in[14];
    const float* linW2  = (const float*)d_in[15];
    const float* linB2  = (const float*)d_in[16];
    const float* W2 = (const float*)d_in[17];
    const float* b2 = (const float*)d_in[18];
    float* out = (float*)d_out;

    const int* src = ei;
    const int* dst = ei + EE;

    // prep (zero deg + both weight rearrangements + both fold GEMMs)
    k_prep<<<422, 256>>>(preW1, preW2, postW1, postB1, linW1, linB1,
                         postW2, postB2, linW2, linB2);
    // CSR build
    k_deg<<<(EE + 255) / 256, 256>>>(dst);
    k_scan<<<1, 1024>>>();
    k_fill<<<(EE + 255) / 256, 256>>>(src, dst);

    // h0 = leaky_relu(x @ W0 + b0)
    k_gemm<128, 64, 1, -1, -1, -1, 0, 0><<<(NN + 127) / 128, 256>>>(x, W0, b0, 0, 0, 0, NN);

    // layer 1
    k_gemm<64, 128, 0, 0, 3, -2, 1, 0><<<(NN + 63) / 64, 256>>>(0, 0, 0, 0, 0, 0, NN);
    k_agg<<<(NN + 3) / 4, 256>>>(preB1);
    k_gemm<320, 64, 2, 2, 5, 7, 0, 0><<<(NN + 127) / 128, 256>>>(0, 0, 0, 0, 0, 0, NN);

    // layer 2 (final GEMM fuses relu + out = h . W2 + b2)
    k_gemm<64, 128, 0, 0, 4, -2, 1, 0><<<(NN + 63) / 64, 256>>>(0, 0, 0, 0, 0, 0, NN);
    k_agg<<<(NN + 3) / 4, 256>>>(preB2);
    k_gemm<320, 64, 2, 2, 6, 8, 0, 1><<<(NN + 127) / 128, 256>>>(0, 0, 0, W2, b2, out, NN);
}